// round 11
// baseline (speedup 1.0000x reference)
#include <cuda_runtime.h>
#include <cuda_fp16.h>
#include <stdint.h>

#define VOCAB   100000
#define DIM     128
#define BATCH   2048
#define ROWS    1000          // V*L
#define NCLASS  128
#define TWO_D   256
#define INV_L   (1.0f / 20.0f)
#define TS      16            // samples per GEMM CTA
#define WPAD4   65            // float4 stride (= 260 floats): 16B-aligned, conflict-free
#define PGRID   1024          // persistent pool grid: exactly one wave (<=1184)

// scratch (allocation-free rule: __device__ globals)
__device__ __half g_embh[(size_t)VOCAB * DIM];   // fp16 embedding table (25.6 MB)
__device__ float  g_x[(size_t)BATCH * TWO_D];    // pooled features (2 MB)

// ---------------------------------------------------------------------------
// 1) emb f32 -> fp16 (R6-exact). 3125 blocks x 4 float4 loads/thread;
//    __ldcs = evict-first so the fp32 stream doesn't evict the fp16 table.
// ---------------------------------------------------------------------------
__global__ __launch_bounds__(256)
void convert_kernel(const float* __restrict__ emb)
{
    const float4* e4 = reinterpret_cast<const float4*>(emb);
    uint2*        o2 = reinterpret_cast<uint2*>(g_embh);   // 1 uint2 = 4 halves

    const int base = blockIdx.x * 1024 + threadIdx.x;

    float4 a0 = __ldcs(&e4[base + 0 * 256]);
    float4 a1 = __ldcs(&e4[base + 1 * 256]);
    float4 a2 = __ldcs(&e4[base + 2 * 256]);
    float4 a3 = __ldcs(&e4[base + 3 * 256]);

    __half2 h00 = __floats2half2_rn(a0.x, a0.y), h01 = __floats2half2_rn(a0.z, a0.w);
    __half2 h10 = __floats2half2_rn(a1.x, a1.y), h11 = __floats2half2_rn(a1.z, a1.w);
    __half2 h20 = __floats2half2_rn(a2.x, a2.y), h21 = __floats2half2_rn(a2.z, a2.w);
    __half2 h30 = __floats2half2_rn(a3.x, a3.y), h31 = __floats2half2_rn(a3.z, a3.w);

    uint2 o0, o1, o2v, o3;
    o0.x  = *reinterpret_cast<uint32_t*>(&h00);  o0.y  = *reinterpret_cast<uint32_t*>(&h01);
    o1.x  = *reinterpret_cast<uint32_t*>(&h10);  o1.y  = *reinterpret_cast<uint32_t*>(&h11);
    o2v.x = *reinterpret_cast<uint32_t*>(&h20);  o2v.y = *reinterpret_cast<uint32_t*>(&h21);
    o3.x  = *reinterpret_cast<uint32_t*>(&h30);  o3.y  = *reinterpret_cast<uint32_t*>(&h31);

    o2[base + 0 * 256] = o0;
    o2[base + 1 * 256] = o1;
    o2[base + 2 * 256] = o2v;
    o2[base + 3 * 256] = o3;
}

// ---------------------------------------------------------------------------
// 2) pooling, persistent single-wave: grid=1024, each CTA does samples
//    b and b+1024 (perfect balance, no wave-2 tail at 73% fill).
//    Inner structure R6-exact: each warp LDG.128 covers 2 fp16 rows.
// ---------------------------------------------------------------------------
__global__ __launch_bounds__(256)
void pool_kernel(const int* __restrict__ diag_idx,
                 const int* __restrict__ proc_idx)
{
    __shared__ int   s_di[ROWS];
    __shared__ int   s_pi[ROWS];
    __shared__ float s_part[2][16][DIM];   // [table][warp*2+half][dim]

    const int tid  = threadIdx.x;
    const int w    = tid >> 5;
    const int lane = tid & 31;
    const int hi   = lane >> 4;            // which row of the pair
    const int lo   = lane & 15;            // 16B chunk within row

    const uint4* eh = reinterpret_cast<const uint4*>(g_embh);  // row = 16 uint4

    for (int b = blockIdx.x; b < BATCH; b += PGRID) {
        __syncthreads();   // previous iter's gather/reduce fully done before re-staging

        const int* gd = diag_idx + b * ROWS;
        const int* gp = proc_idx + b * ROWS;
        for (int i = tid; i < ROWS; i += 256) {
            s_di[i] = __ldcs(&gd[i]);      // read-once streams
            s_pi[i] = __ldcs(&gp[i]);
        }
        __syncthreads();

        float fd[8] = {0.f, 0.f, 0.f, 0.f, 0.f, 0.f, 0.f, 0.f};
        float fp[8] = {0.f, 0.f, 0.f, 0.f, 0.f, 0.f, 0.f, 0.f};

        #pragma unroll 4
        for (int p = w; p < ROWS / 2; p += 8) {       // 500 row-pairs
            const int rd = s_di[2 * p + hi];
            const int rp = s_pi[2 * p + hi];
            const uint4 vd = eh[rd * 16 + lo];
            const uint4 vp = eh[rp * 16 + lo];
            const __half2* hd = reinterpret_cast<const __half2*>(&vd);
            const __half2* hp = reinterpret_cast<const __half2*>(&vp);
            #pragma unroll
            for (int j = 0; j < 4; j++) {
                float2 d2 = __half22float2(hd[j]);
                float2 p2 = __half22float2(hp[j]);
                fd[2 * j + 0] += d2.x;  fd[2 * j + 1] += d2.y;
                fp[2 * j + 0] += p2.x;  fp[2 * j + 1] += p2.y;
            }
        }

        // per-(warp,half) partials: dims lo*8 .. lo*8+7
        float* dd = &s_part[0][w * 2 + hi][lo * 8];
        float* dp = &s_part[1][w * 2 + hi][lo * 8];
        *reinterpret_cast<float4*>(dd + 0) = make_float4(fd[0], fd[1], fd[2], fd[3]);
        *reinterpret_cast<float4*>(dd + 4) = make_float4(fd[4], fd[5], fd[6], fd[7]);
        *reinterpret_cast<float4*>(dp + 0) = make_float4(fp[0], fp[1], fp[2], fp[3]);
        *reinterpret_cast<float4*>(dp + 4) = make_float4(fp[4], fp[5], fp[6], fp[7]);
        __syncthreads();

        // cross-warp reduce -> g_x[b, 0:128]=diag, [128:256]=proc
        const int sel = tid >> 7;
        const int d   = tid & (DIM - 1);
        float s = 0.f;
        #pragma unroll
        for (int q = 0; q < 16; q++) s += s_part[sel][q][d];
        g_x[(size_t)b * TWO_D + sel * DIM + d] = s * INV_L;
    }
}

// ---------------------------------------------------------------------------
// 3) GEMM epilogue (R6-exact): out[s,c] = sum_k x[s,k] * W[c,k] + b[c]
//    float4 smem tiles (LDS.128), stride WPAD4=65 float4 -> conflict-free.
// ---------------------------------------------------------------------------
__global__ __launch_bounds__(256)
void gemm_kernel(const float* __restrict__ W,
                 const float* __restrict__ bias,
                 float*       __restrict__ out)
{
    extern __shared__ float4 sh4[];
    float4* sW = sh4;                        // [128][WPAD4]
    float4* sx = sh4 + NCLASS * WPAD4;       // [TS][WPAD4]

    const int tid  = threadIdx.x;
    const int base = blockIdx.x * TS;

    const float4* W4 = reinterpret_cast<const float4*>(W);            // [128][64]
    const float4* x4 = reinterpret_cast<const float4*>(g_x + (size_t)base * TWO_D); // [TS][64]

    #pragma unroll
    for (int i = tid; i < NCLASS * (TWO_D / 4); i += 256) {
        const int c = i >> 6, kq = i & 63;
        sW[c * WPAD4 + kq] = W4[i];
    }
    #pragma unroll
    for (int i = tid; i < TS * (TWO_D / 4); i += 256) {
        const int s = i >> 6, kq = i & 63;
        sx[s * WPAD4 + kq] = x4[i];
    }
    __syncthreads();

    const int w    = tid >> 5;
    const int lane = tid & 31;
    const int s0   = w * 2, s1 = s0 + 1;

    float acc[2][4] = {};
    #pragma unroll 8
    for (int kq = 0; kq < TWO_D / 4; kq++) {
        const float4 x0 = sx[s0 * WPAD4 + kq];
        const float4 x1 = sx[s1 * WPAD4 + kq];
        #pragma unroll
        for (int cu = 0; cu < 4; cu++) {
            const float4 wv = sW[(lane + cu * 32) * WPAD4 + kq];
            acc[0][cu] += x0.x * wv.x + x0.y * wv.y + x0.z * wv.z + x0.w * wv.w;
            acc[1][cu] += x1.x * wv.x + x1.y * wv.y + x1.z * wv.z + x1.w * wv.w;
        }
    }

    #pragma unroll
    for (int cu = 0; cu < 4; cu++) {
        const int c = lane + cu * 32;
        const float bc = bias[c];
        out[(size_t)(base + s0) * NCLASS + c] = acc[0][cu] + bc;
        out[(size_t)(base + s1) * NCLASS + c] = acc[1][cu] + bc;
    }
}

// ---------------------------------------------------------------------------
extern "C" void kernel_launch(void* const* d_in, const int* in_sizes, int n_in,
                              void* d_out, int out_size)
{
    const int*   diag_idx = (const int*)  d_in[0];
    const int*   proc_idx = (const int*)  d_in[1];
    const float* emb      = (const float*)d_in[2];
    const float* W        = (const float*)d_in[3];
    const float* bias     = (const float*)d_in[4];
    float*       out      = (float*)d_out;

    const int gemm_smem = (NCLASS + TS) * WPAD4 * sizeof(float4);   // 149760 B
    cudaFuncSetAttribute(gemm_kernel,
                         cudaFuncAttributeMaxDynamicSharedMemorySize, gemm_smem);

    convert_kernel<<<3125, 256>>>(emb);                 // 12.8M f32 -> fp16
    pool_kernel<<<PGRID, 256>>>(diag_idx, proc_idx);    // single-wave persistent
    gemm_kernel<<<BATCH / TS, 256, gemm_smem>>>(W, bias, out);
}

// round 12
// speedup vs baseline: 1.1373x; 1.1373x over previous
#include <cuda_runtime.h>
#include <cuda_fp16.h>
#include <stdint.h>

#define VOCAB   100000
#define DIM     128
#define BATCH   2048
#define ROWS    1000          // V*L
#define NCLASS  128
#define TWO_D   256
#define INV_L   (1.0f / 20.0f)
#define TS      16            // samples per GEMM CTA
#define WPAD4   65            // float4 stride (= 260 floats): 16B-aligned, conflict-free

// scratch (allocation-free rule: __device__ globals)
__device__ __half g_embh[(size_t)VOCAB * DIM];   // fp16 embedding table (25.6 MB)
__device__ float  g_x[(size_t)BATCH * TWO_D];    // pooled features (2 MB)

// ---------------------------------------------------------------------------
// 1) emb f32 -> fp16 (R6-exact: part of best-measured 86.2us config).
//    3125 blocks x 4 float4 loads/thread; __ldcs = evict-first so the fp32
//    stream doesn't evict the fp16 table from L2.
// ---------------------------------------------------------------------------
__global__ __launch_bounds__(256)
void convert_kernel(const float* __restrict__ emb)
{
    const float4* e4 = reinterpret_cast<const float4*>(emb);
    uint2*        o2 = reinterpret_cast<uint2*>(g_embh);   // 1 uint2 = 4 halves

    const int base = blockIdx.x * 1024 + threadIdx.x;

    float4 a0 = __ldcs(&e4[base + 0 * 256]);
    float4 a1 = __ldcs(&e4[base + 1 * 256]);
    float4 a2 = __ldcs(&e4[base + 2 * 256]);
    float4 a3 = __ldcs(&e4[base + 3 * 256]);

    __half2 h00 = __floats2half2_rn(a0.x, a0.y), h01 = __floats2half2_rn(a0.z, a0.w);
    __half2 h10 = __floats2half2_rn(a1.x, a1.y), h11 = __floats2half2_rn(a1.z, a1.w);
    __half2 h20 = __floats2half2_rn(a2.x, a2.y), h21 = __floats2half2_rn(a2.z, a2.w);
    __half2 h30 = __floats2half2_rn(a3.x, a3.y), h31 = __floats2half2_rn(a3.z, a3.w);

    uint2 o0, o1, o2v, o3;
    o0.x  = *reinterpret_cast<uint32_t*>(&h00);  o0.y  = *reinterpret_cast<uint32_t*>(&h01);
    o1.x  = *reinterpret_cast<uint32_t*>(&h10);  o1.y  = *reinterpret_cast<uint32_t*>(&h11);
    o2v.x = *reinterpret_cast<uint32_t*>(&h20);  o2v.y = *reinterpret_cast<uint32_t*>(&h21);
    o3.x  = *reinterpret_cast<uint32_t*>(&h30);  o3.y  = *reinterpret_cast<uint32_t*>(&h31);

    o2[base + 0 * 256] = o0;
    o2[base + 1 * 256] = o1;
    o2[base + 2 * 256] = o2v;
    o2[base + 3 * 256] = o3;
}

// ---------------------------------------------------------------------------
// 2) pooling (R6-exact: best measured). One CTA per sample; each warp
//    LDG.128 covers 2 fp16 rows. At the LTS bandwidth cap.
// ---------------------------------------------------------------------------
__global__ __launch_bounds__(256)
void pool_kernel(const int* __restrict__ diag_idx,
                 const int* __restrict__ proc_idx)
{
    __shared__ int   s_di[ROWS];
    __shared__ int   s_pi[ROWS];
    __shared__ float s_part[2][16][DIM];   // [table][warp*2+half][dim]

    const int b    = blockIdx.x;
    const int tid  = threadIdx.x;
    const int w    = tid >> 5;
    const int lane = tid & 31;
    const int hi   = lane >> 4;            // which row of the pair
    const int lo   = lane & 15;            // 16B chunk within row

    const int* gd = diag_idx + b * ROWS;
    const int* gp = proc_idx + b * ROWS;
    for (int i = tid; i < ROWS; i += 256) {
        s_di[i] = __ldcs(&gd[i]);          // read-once streams
        s_pi[i] = __ldcs(&gp[i]);
    }
    __syncthreads();

    const uint4* eh = reinterpret_cast<const uint4*>(g_embh);  // row = 16 uint4

    float fd[8] = {0.f, 0.f, 0.f, 0.f, 0.f, 0.f, 0.f, 0.f};
    float fp[8] = {0.f, 0.f, 0.f, 0.f, 0.f, 0.f, 0.f, 0.f};

    #pragma unroll 4
    for (int p = w; p < ROWS / 2; p += 8) {           // 500 row-pairs
        const int rd = s_di[2 * p + hi];
        const int rp = s_pi[2 * p + hi];
        const uint4 vd = eh[rd * 16 + lo];
        const uint4 vp = eh[rp * 16 + lo];
        const __half2* hd = reinterpret_cast<const __half2*>(&vd);
        const __half2* hp = reinterpret_cast<const __half2*>(&vp);
        #pragma unroll
        for (int j = 0; j < 4; j++) {
            float2 d2 = __half22float2(hd[j]);
            float2 p2 = __half22float2(hp[j]);
            fd[2 * j + 0] += d2.x;  fd[2 * j + 1] += d2.y;
            fp[2 * j + 0] += p2.x;  fp[2 * j + 1] += p2.y;
        }
    }

    // per-(warp,half) partials: dims lo*8 .. lo*8+7
    float* dd = &s_part[0][w * 2 + hi][lo * 8];
    float* dp = &s_part[1][w * 2 + hi][lo * 8];
    *reinterpret_cast<float4*>(dd + 0) = make_float4(fd[0], fd[1], fd[2], fd[3]);
    *reinterpret_cast<float4*>(dd + 4) = make_float4(fd[4], fd[5], fd[6], fd[7]);
    *reinterpret_cast<float4*>(dp + 0) = make_float4(fp[0], fp[1], fp[2], fp[3]);
    *reinterpret_cast<float4*>(dp + 4) = make_float4(fp[4], fp[5], fp[6], fp[7]);
    __syncthreads();

    // cross-warp reduce -> g_x[b, 0:128]=diag, [128:256]=proc
    const int sel = tid >> 7;
    const int d   = tid & (DIM - 1);
    float s = 0.f;
    #pragma unroll
    for (int q = 0; q < 16; q++) s += s_part[sel][q][d];
    g_x[(size_t)b * TWO_D + sel * DIM + d] = s * INV_L;
}

// ---------------------------------------------------------------------------
// 3) GEMM epilogue (R6-exact): out[s,c] = sum_k x[s,k] * W[c,k] + b[c]
//    float4 smem tiles (LDS.128), stride WPAD4=65 float4 -> conflict-free.
// ---------------------------------------------------------------------------
__global__ __launch_bounds__(256)
void gemm_kernel(const float* __restrict__ W,
                 const float* __restrict__ bias,
                 float*       __restrict__ out)
{
    extern __shared__ float4 sh4[];
    float4* sW = sh4;                        // [128][WPAD4]
    float4* sx = sh4 + NCLASS * WPAD4;       // [TS][WPAD4]

    const int tid  = threadIdx.x;
    const int base = blockIdx.x * TS;

    const float4* W4 = reinterpret_cast<const float4*>(W);            // [128][64]
    const float4* x4 = reinterpret_cast<const float4*>(g_x + (size_t)base * TWO_D); // [TS][64]

    #pragma unroll
    for (int i = tid; i < NCLASS * (TWO_D / 4); i += 256) {
        const int c = i >> 6, kq = i & 63;
        sW[c * WPAD4 + kq] = W4[i];
    }
    #pragma unroll
    for (int i = tid; i < TS * (TWO_D / 4); i += 256) {
        const int s = i >> 6, kq = i & 63;
        sx[s * WPAD4 + kq] = x4[i];
    }
    __syncthreads();

    const int w    = tid >> 5;
    const int lane = tid & 31;
    const int s0   = w * 2, s1 = s0 + 1;

    float acc[2][4] = {};
    #pragma unroll 8
    for (int kq = 0; kq < TWO_D / 4; kq++) {
        const float4 x0 = sx[s0 * WPAD4 + kq];
        const float4 x1 = sx[s1 * WPAD4 + kq];
        #pragma unroll
        for (int cu = 0; cu < 4; cu++) {
            const float4 wv = sW[(lane + cu * 32) * WPAD4 + kq];
            acc[0][cu] += x0.x * wv.x + x0.y * wv.y + x0.z * wv.z + x0.w * wv.w;
            acc[1][cu] += x1.x * wv.x + x1.y * wv.y + x1.z * wv.z + x1.w * wv.w;
        }
    }

    #pragma unroll
    for (int cu = 0; cu < 4; cu++) {
        const int c = lane + cu * 32;
        const float bc = bias[c];
        out[(size_t)(base + s0) * NCLASS + c] = acc[0][cu] + bc;
        out[(size_t)(base + s1) * NCLASS + c] = acc[1][cu] + bc;
    }
}

// ---------------------------------------------------------------------------
extern "C" void kernel_launch(void* const* d_in, const int* in_sizes, int n_in,
                              void* d_out, int out_size)
{
    const int*   diag_idx = (const int*)  d_in[0];
    const int*   proc_idx = (const int*)  d_in[1];
    const float* emb      = (const float*)d_in[2];
    const float* W        = (const float*)d_in[3];
    const float* bias     = (const float*)d_in[4];
    float*       out      = (float*)d_out;

    const int gemm_smem = (NCLASS + TS) * WPAD4 * sizeof(float4);   // 149760 B
    cudaFuncSetAttribute(gemm_kernel,
                         cudaFuncAttributeMaxDynamicSharedMemorySize, gemm_smem);

    convert_kernel<<<3125, 256>>>(emb);                 // 12.8M f32 -> fp16
    pool_kernel<<<BATCH, 256>>>(diag_idx, proc_idx);
    gemm_kernel<<<BATCH / TS, 256, gemm_smem>>>(W, bias, out);
}

// round 13
// speedup vs baseline: 1.1884x; 1.0449x over previous
#include <cuda_runtime.h>
#include <cuda_fp16.h>
#include <stdint.h>

#define VOCAB   100000
#define DIM     128
#define BATCH   2048
#define ROWS    1000          // V*L
#define NCLASS  128
#define TWO_D   256
#define INV_L   (1.0f / 20.0f)
#define TS      16            // samples per GEMM CTA
#define CH      64            // classes per GEMM CTA (class-split)
#define WPAD4   65            // float4 stride (= 260 floats): 16B-aligned, conflict-free

// scratch (allocation-free rule: __device__ globals)
__device__ __half g_embh[(size_t)VOCAB * DIM];   // fp16 embedding table (25.6 MB)
__device__ float  g_x[(size_t)BATCH * TWO_D];    // pooled features (2 MB)

// ---------------------------------------------------------------------------
// 1) emb f32 -> fp16, hybrid best shape: each thread handles TWO adjacent-pair
//    groups (j and j+256): 4 LDG.128 (MLP=4) + 2 STG.128 (fastest measured
//    store path). 3125 blocks x 256 thr x 4 float4. __ldcs = evict-first so
//    the fp32 stream doesn't evict the fp16 table from L2.
// ---------------------------------------------------------------------------
__global__ __launch_bounds__(256)
void convert_kernel(const float* __restrict__ emb)
{
    const float4* e4 = reinterpret_cast<const float4*>(emb);
    uint4*        o4 = reinterpret_cast<uint4*>(g_embh);    // 1 uint4 = 8 halves

    const int j0 = blockIdx.x * 512 + threadIdx.x;          // uint4 output idx
    const int j1 = j0 + 256;

    float4 a0 = __ldcs(&e4[2 * j0 + 0]);
    float4 a1 = __ldcs(&e4[2 * j0 + 1]);
    float4 b0 = __ldcs(&e4[2 * j1 + 0]);
    float4 b1 = __ldcs(&e4[2 * j1 + 1]);

    __half2 ha0 = __floats2half2_rn(a0.x, a0.y), ha1 = __floats2half2_rn(a0.z, a0.w);
    __half2 ha2 = __floats2half2_rn(a1.x, a1.y), ha3 = __floats2half2_rn(a1.z, a1.w);
    __half2 hb0 = __floats2half2_rn(b0.x, b0.y), hb1 = __floats2half2_rn(b0.z, b0.w);
    __half2 hb2 = __floats2half2_rn(b1.x, b1.y), hb3 = __floats2half2_rn(b1.z, b1.w);

    uint4 oa, ob;
    oa.x = *reinterpret_cast<uint32_t*>(&ha0);  oa.y = *reinterpret_cast<uint32_t*>(&ha1);
    oa.z = *reinterpret_cast<uint32_t*>(&ha2);  oa.w = *reinterpret_cast<uint32_t*>(&ha3);
    ob.x = *reinterpret_cast<uint32_t*>(&hb0);  ob.y = *reinterpret_cast<uint32_t*>(&hb1);
    ob.z = *reinterpret_cast<uint32_t*>(&hb2);  ob.w = *reinterpret_cast<uint32_t*>(&hb3);

    o4[j0] = oa;
    o4[j1] = ob;
}

// ---------------------------------------------------------------------------
// 2) pooling (R6-exact, FROZEN: at the LTS bandwidth cap). One CTA per
//    sample; each warp LDG.128 covers 2 fp16 rows.
// ---------------------------------------------------------------------------
__global__ __launch_bounds__(256)
void pool_kernel(const int* __restrict__ diag_idx,
                 const int* __restrict__ proc_idx)
{
    __shared__ int   s_di[ROWS];
    __shared__ int   s_pi[ROWS];
    __shared__ float s_part[2][16][DIM];   // [table][warp*2+half][dim]

    const int b    = blockIdx.x;
    const int tid  = threadIdx.x;
    const int w    = tid >> 5;
    const int lane = tid & 31;
    const int hi   = lane >> 4;            // which row of the pair
    const int lo   = lane & 15;            // 16B chunk within row

    const int* gd = diag_idx + b * ROWS;
    const int* gp = proc_idx + b * ROWS;
    for (int i = tid; i < ROWS; i += 256) {
        s_di[i] = __ldcs(&gd[i]);          // read-once streams
        s_pi[i] = __ldcs(&gp[i]);
    }
    __syncthreads();

    const uint4* eh = reinterpret_cast<const uint4*>(g_embh);  // row = 16 uint4

    float fd[8] = {0.f, 0.f, 0.f, 0.f, 0.f, 0.f, 0.f, 0.f};
    float fp[8] = {0.f, 0.f, 0.f, 0.f, 0.f, 0.f, 0.f, 0.f};

    #pragma unroll 4
    for (int p = w; p < ROWS / 2; p += 8) {           // 500 row-pairs
        const int rd = s_di[2 * p + hi];
        const int rp = s_pi[2 * p + hi];
        const uint4 vd = eh[rd * 16 + lo];
        const uint4 vp = eh[rp * 16 + lo];
        const __half2* hd = reinterpret_cast<const __half2*>(&vd);
        const __half2* hp = reinterpret_cast<const __half2*>(&vp);
        #pragma unroll
        for (int j = 0; j < 4; j++) {
            float2 d2 = __half22float2(hd[j]);
            float2 p2 = __half22float2(hp[j]);
            fd[2 * j + 0] += d2.x;  fd[2 * j + 1] += d2.y;
            fp[2 * j + 0] += p2.x;  fp[2 * j + 1] += p2.y;
        }
    }

    // per-(warp,half) partials: dims lo*8 .. lo*8+7
    float* dd = &s_part[0][w * 2 + hi][lo * 8];
    float* dp = &s_part[1][w * 2 + hi][lo * 8];
    *reinterpret_cast<float4*>(dd + 0) = make_float4(fd[0], fd[1], fd[2], fd[3]);
    *reinterpret_cast<float4*>(dd + 4) = make_float4(fd[4], fd[5], fd[6], fd[7]);
    *reinterpret_cast<float4*>(dp + 0) = make_float4(fp[0], fp[1], fp[2], fp[3]);
    *reinterpret_cast<float4*>(dp + 4) = make_float4(fp[4], fp[5], fp[6], fp[7]);
    __syncthreads();

    // cross-warp reduce -> g_x[b, 0:128]=diag, [128:256]=proc
    const int sel = tid >> 7;
    const int d   = tid & (DIM - 1);
    float s = 0.f;
    #pragma unroll
    for (int q = 0; q < 16; q++) s += s_part[sel][q][d];
    g_x[(size_t)b * TWO_D + sel * DIM + d] = s * INV_L;
}

// ---------------------------------------------------------------------------
// 3) GEMM epilogue, class-split: each CTA does CH=64 classes x TS=16 samples.
//    smem = (64+16)*65*16B = 83.2 KB -> 2 CTAs/SM, 256 CTAs (full chip).
//    float4 smem tiles (LDS.128), stride WPAD4=65 -> conflict-free.
// ---------------------------------------------------------------------------
__global__ __launch_bounds__(256)
void gemm_kernel(const float* __restrict__ W,
                 const float* __restrict__ bias,
                 float*       __restrict__ out)
{
    extern __shared__ float4 sh4[];
    float4* sW = sh4;                        // [CH][WPAD4]
    float4* sx = sh4 + CH * WPAD4;           // [TS][WPAD4]

    const int tid   = threadIdx.x;
    const int sblk  = blockIdx.x >> 1;       // sample block
    const int chalf = blockIdx.x & 1;        // class half (0 or 1)
    const int base  = sblk * TS;
    const int cbase = chalf * CH;

    const float4* W4 = reinterpret_cast<const float4*>(W) + (size_t)cbase * (TWO_D / 4);
    const float4* x4 = reinterpret_cast<const float4*>(g_x + (size_t)base * TWO_D);

    #pragma unroll
    for (int i = tid; i < CH * (TWO_D / 4); i += 256) {
        const int c = i >> 6, kq = i & 63;
        sW[c * WPAD4 + kq] = W4[i];
    }
    #pragma unroll
    for (int i = tid; i < TS * (TWO_D / 4); i += 256) {
        const int s = i >> 6, kq = i & 63;
        sx[s * WPAD4 + kq] = x4[i];
    }
    __syncthreads();

    const int w    = tid >> 5;
    const int lane = tid & 31;
    const int s0   = w * 2, s1 = s0 + 1;

    float acc[2][2] = {};
    #pragma unroll 8
    for (int kq = 0; kq < TWO_D / 4; kq++) {
        const float4 x0 = sx[s0 * WPAD4 + kq];
        const float4 x1 = sx[s1 * WPAD4 + kq];
        #pragma unroll
        for (int cu = 0; cu < 2; cu++) {
            const float4 wv = sW[(lane + cu * 32) * WPAD4 + kq];
            acc[0][cu] += x0.x * wv.x + x0.y * wv.y + x0.z * wv.z + x0.w * wv.w;
            acc[1][cu] += x1.x * wv.x + x1.y * wv.y + x1.z * wv.z + x1.w * wv.w;
        }
    }

    #pragma unroll
    for (int cu = 0; cu < 2; cu++) {
        const int c = cbase + lane + cu * 32;
        const float bc = bias[c];
        out[(size_t)(base + s0) * NCLASS + c] = acc[0][cu] + bc;
        out[(size_t)(base + s1) * NCLASS + c] = acc[1][cu] + bc;
    }
}

// ---------------------------------------------------------------------------
extern "C" void kernel_launch(void* const* d_in, const int* in_sizes, int n_in,
                              void* d_out, int out_size)
{
    const int*   diag_idx = (const int*)  d_in[0];
    const int*   proc_idx = (const int*)  d_in[1];
    const float* emb      = (const float*)d_in[2];
    const float* W        = (const float*)d_in[3];
    const float* bias     = (const float*)d_in[4];
    float*       out      = (float*)d_out;

    const int gemm_smem = (CH + TS) * WPAD4 * sizeof(float4);   // 83200 B
    cudaFuncSetAttribute(gemm_kernel,
                         cudaFuncAttributeMaxDynamicSharedMemorySize, gemm_smem);

    convert_kernel<<<3125, 256>>>(emb);                  // 12.8M f32 -> fp16
    pool_kernel<<<BATCH, 256>>>(diag_idx, proc_idx);
    gemm_kernel<<<(BATCH / TS) * 2, 256, gemm_smem>>>(W, bias, out);
}